// round 10
// baseline (speedup 1.0000x reference)
#include <cuda_runtime.h>
#include <cstdint>
#include <cstddef>

#define T_DIM 512
#define B_DIM 64
#define I_DIM 512
#define H_DIM 512
#define NCTA 128
#define HS_STRIDE 516  /* 512 + 4 pad */

typedef unsigned long long ull;

// ---------------- device scratch (allocation-free: __device__ globals) ----------------
__device__ float g_xn[(size_t)T_DIM * B_DIM * H_DIM];   // 64 MB precomputed input projection
__device__ float g_xz[T_DIM * B_DIM];
__device__ float g_xr[T_DIM * B_DIM];
__device__ float g_hbuf[2][B_DIM * H_DIM];              // double-buffered hidden state
__device__ unsigned g_count;                             // barrier arrival counter
__device__ unsigned g_gen;                               // barrier generation

// ---------------- packed f32x2 helpers (Blackwell FFMA2) ----------------
__device__ __forceinline__ ull ffma2(ull a, ull b, ull c) {
    ull d; asm("fma.rn.f32x2 %0, %1, %2, %3;" : "=l"(d) : "l"(a), "l"(b), "l"(c)); return d;
}
__device__ __forceinline__ ull fpack2(float x, float y) {
    ull d; asm("mov.b64 %0, {%1, %2};" : "=l"(d) : "f"(x), "f"(y)); return d;
}
__device__ __forceinline__ float2 funpack2(ull a) {
    float2 r; asm("mov.b64 {%0, %1}, %2;" : "=f"(r.x), "=f"(r.y) : "l"(a)); return r;
}
__device__ __forceinline__ unsigned ld_acquire_gpu(unsigned* p) {
    unsigned v; asm volatile("ld.acquire.gpu.u32 %0, [%1];" : "=r"(v) : "l"(p) : "memory");
    return v;
}

// ---------------- kernel 1: xz/xr projections (warp per row) + barrier state reset ----
__global__ void k_xzr(const float* __restrict__ inp, const float* __restrict__ zw,
                      const float* __restrict__ zb, const float* __restrict__ rw,
                      const float* __restrict__ rb) {
    if (blockIdx.x == 0 && threadIdx.x == 0) { g_count = 0; g_gen = 0; }
    int gw   = (blockIdx.x * blockDim.x + threadIdx.x) >> 5;
    int lane = threadIdx.x & 31;
    if (gw >= T_DIM * B_DIM) return;
    const float4* row = (const float4*)(inp + (size_t)gw * I_DIM);
    const float4* z4  = (const float4*)zw;
    const float4* r4  = (const float4*)rw;
    float za = 0.f, ra = 0.f;
#pragma unroll
    for (int i = 0; i < 4; i++) {
        float4 v  = row[lane + 32 * i];
        float4 zz = __ldg(&z4[lane + 32 * i]);
        float4 rr = __ldg(&r4[lane + 32 * i]);
        za += v.x * zz.x + v.y * zz.y + v.z * zz.z + v.w * zz.w;
        ra += v.x * rr.x + v.y * rr.y + v.z * rr.z + v.w * rr.w;
    }
#pragma unroll
    for (int off = 16; off > 0; off >>= 1) {
        za += __shfl_down_sync(0xffffffffu, za, off);
        ra += __shfl_down_sync(0xffffffffu, ra, off);
    }
    if (lane == 0) {
        g_xz[gw] = za + __ldg(zb);
        g_xr[gw] = ra + __ldg(rb);
    }
}

// ---------------- kernel 2: xn = input @ h_w_w^T + h_w_b  (FFMA2 SGEMM) ----------------
#define BM 128
#define BN 128
#define BK 16
__global__ __launch_bounds__(256) void k_xn(const float* __restrict__ A,
                                            const float* __restrict__ W,
                                            const float* __restrict__ bias) {
    __shared__ float As[BK][BM + 4];
    __shared__ float Bs[BK][BN + 4];
    const int tid  = threadIdx.x;
    const int mblk = blockIdx.y * BM;
    const int nblk = blockIdx.x * BN;
    const int tn   = (tid & 15) * 8;
    const int tm   = (tid >> 4) * 8;

    ull acc[8][4];
#pragma unroll
    for (int i = 0; i < 8; i++)
#pragma unroll
        for (int p = 0; p < 4; p++) acc[i][p] = 0ull;

    for (int k0 = 0; k0 < I_DIM; k0 += BK) {
#pragma unroll
        for (int i = 0; i < 2; i++) {
            int id = tid + 256 * i;
            int m = id >> 2, kq = id & 3;
            float4 av = *(const float4*)(A + (size_t)(mblk + m) * I_DIM + k0 + kq * 4);
            As[kq * 4 + 0][m] = av.x; As[kq * 4 + 1][m] = av.y;
            As[kq * 4 + 2][m] = av.z; As[kq * 4 + 3][m] = av.w;
            float4 bv = *(const float4*)(W + (size_t)(nblk + m) * I_DIM + k0 + kq * 4);
            Bs[kq * 4 + 0][m] = bv.x; Bs[kq * 4 + 1][m] = bv.y;
            Bs[kq * 4 + 2][m] = bv.z; Bs[kq * 4 + 3][m] = bv.w;
        }
        __syncthreads();
#pragma unroll
        for (int k = 0; k < BK; k++) {
            float4 a0 = *(const float4*)&As[k][tm];
            float4 a1 = *(const float4*)&As[k][tm + 4];
            ulonglong2 b0 = *(const ulonglong2*)&Bs[k][tn];
            ulonglong2 b1 = *(const ulonglong2*)&Bs[k][tn + 4];
            ull bb[4] = { b0.x, b0.y, b1.x, b1.y };
            float a[8] = { a0.x, a0.y, a0.z, a0.w, a1.x, a1.y, a1.z, a1.w };
#pragma unroll
            for (int i = 0; i < 8; i++) {
                ull ad = fpack2(a[i], a[i]);
#pragma unroll
                for (int p = 0; p < 4; p++) acc[i][p] = ffma2(ad, bb[p], acc[i][p]);
            }
        }
        __syncthreads();
    }
    float4 bvlo = *(const float4*)(bias + nblk + tn);
    float4 bvhi = *(const float4*)(bias + nblk + tn + 4);
#pragma unroll
    for (int i = 0; i < 8; i++) {
        float2 c0 = funpack2(acc[i][0]);
        float2 c1 = funpack2(acc[i][1]);
        float2 c2 = funpack2(acc[i][2]);
        float2 c3 = funpack2(acc[i][3]);
        float4 o0 = make_float4(c0.x + bvlo.x, c0.y + bvlo.y, c1.x + bvlo.z, c1.y + bvlo.w);
        float4 o1 = make_float4(c2.x + bvhi.x, c2.y + bvhi.y, c3.x + bvhi.z, c3.y + bvhi.w);
        float* outp = g_xn + (size_t)(mblk + tm + i) * H_DIM + nblk + tn;
        *(float4*)outp       = o0;
        *(float4*)(outp + 4) = o1;
    }
}

// ---------------- kernel 3: persistent GRU scan ----------------
// Grid: 128 CTAs = 32 col-groups x 4 batch-groups. Each CTA owns a 16(b) x 16(h) tile.
// h_u_w tile lives in REGISTERS (32 floats/thread). h tile (16x512) staged in smem/step.
// Global sense-reversing barrier (nanosleep backoff) between steps.
// xn/xz/xr for step t+1 are prefetched BEFORE the barrier (g_xn is immutable here).
#define SCAN_SMEM_FLOATS (16 * HS_STRIDE + 16 * 16 * 17 + 512 + 576 + 576 + 16 + 16)
#define SCAN_SMEM_BYTES  (SCAN_SMEM_FLOATS * 4)

__global__ __launch_bounds__(256) void k_scan(
    const float* __restrict__ hidden, const float* __restrict__ huw,
    const float* __restrict__ hub, const float* __restrict__ zuw,
    const float* __restrict__ zubp, const float* __restrict__ ruw,
    const float* __restrict__ rubp, float* __restrict__ out,
    float* __restrict__ hid_out) {
    extern __shared__ float sm[];
    float* h_s  = sm;                         // [16][HS_STRIDE]
    float* red  = sm + 16 * HS_STRIDE;        // [16b][16j][17] partials
    float* zrj  = red + 16 * 16 * 17;         // float2 [16 ks][16 b] gate partials
    float* zu_s = zrj + 512;                  // padded: idx k + 4*(k>>5)
    float* ru_s = zu_s + 576;
    float* zg_s = ru_s + 576;                 // [16]
    float* rg_s = zg_s + 16;                  // [16]

    const int tid = threadIdx.x;
    const int cg  = blockIdx.x & 31;   // col group
    const int bg  = blockIdx.x >> 5;   // batch group
    const int j   = tid & 15;
    const int ks  = tid >> 4;          // k-slice (32 k's each)
    const int jg  = cg * 16 + j;

    // h_u_w slice in registers: 32 floats = 16 packed pairs
    ull u2[16];
    {
        const ulonglong2* up = (const ulonglong2*)(huw + (size_t)jg * H_DIM + ks * 32);
#pragma unroll
        for (int q = 0; q < 8; q++) { ulonglong2 v = up[q]; u2[2 * q] = v.x; u2[2 * q + 1] = v.y; }
    }
    const float zub  = *zubp;
    const float rub  = *rubp;
    const float hubv = hub[jg];
    for (int i = tid; i < 512; i += 256) {
        int d = i + 4 * (i >> 5);
        zu_s[d] = zuw[i];
        ru_s[d] = ruw[i];
    }
    const int gb  = tid & 15, gks = tid >> 4;   // gate-phase mapping
    const int pb  = tid >> 4, pj = tid & 15;    // phase-2 mapping (pj == j)
    const int pbg = bg * 16 + pb;
    unsigned gen_expect = 1;
    __syncthreads();

    // prefetch step-0 time-parallel terms
    float xn_v  = __ldg(&g_xn[((size_t)0 * B_DIM + pbg) * H_DIM + jg]);
    float xzr_v = 0.f;
    if (pj == 0)      xzr_v = __ldg(&g_xz[pbg]);
    else if (pj == 1) xzr_v = __ldg(&g_xr[pbg]);

    for (int t = 0; t < T_DIM; t++) {
        const float* hsrc = (t == 0) ? hidden : g_hbuf[(t + 1) & 1];

        // stage h tile 16x512 into smem (L2 loads; other SMs wrote it)
#pragma unroll
        for (int i = 0; i < 8; i++) {
            int id = i * 256 + tid;
            int r = id >> 7, c4 = id & 127;
            float4 v = __ldcg((const float4*)(hsrc + (size_t)(bg * 16 + r) * H_DIM) + c4);
            *(float4*)&h_s[r * HS_STRIDE + c4 * 4] = v;
        }
        __syncthreads();

        // gate partial dots (z and r), per (batch, k-slice)
        {
            ull za = 0ull, ra = 0ull;
#pragma unroll
            for (int c = 0; c < 8; c++) {
                ulonglong2 hv = *(const ulonglong2*)&h_s[gb * HS_STRIDE + gks * 32 + c * 4];
                ulonglong2 zv = *(const ulonglong2*)&zu_s[gks * 36 + c * 4];
                ulonglong2 rv = *(const ulonglong2*)&ru_s[gks * 36 + c * 4];
                za = ffma2(hv.x, zv.x, za); za = ffma2(hv.y, zv.y, za);
                ra = ffma2(hv.x, rv.x, ra); ra = ffma2(hv.y, rv.y, ra);
            }
            float2 zf = funpack2(za), rf = funpack2(ra);
            ((float2*)zrj)[gks * 16 + gb] = make_float2(zf.x + zf.y, rf.x + rf.y);
        }

        // main GEMM partials: h[16 b, 32 k] . u2 (registers); h LDS is 16-lane broadcast
        {
            ull acc[16];
#pragma unroll
            for (int b = 0; b < 16; b++) acc[b] = 0ull;
#pragma unroll
            for (int c = 0; c < 8; c++) {
                ull ua = u2[2 * c], ub = u2[2 * c + 1];
#pragma unroll
                for (int b = 0; b < 16; b++) {
                    ulonglong2 hv = *(const ulonglong2*)&h_s[b * HS_STRIDE + ks * 32 + c * 4];
                    acc[b] = ffma2(hv.x, ua, acc[b]);
                    acc[b] = ffma2(hv.y, ub, acc[b]);
                }
            }
#pragma unroll
            for (int b = 0; b < 16; b++) {
                float2 f = funpack2(acc[b]);
                red[(b * 16 + j) * 17 + ks] = f.x + f.y;
            }
        }
        __syncthreads();

        // phase 2: reduce k-slices; finalize gates; elementwise GRU update
        float dot = 0.f;
#pragma unroll
        for (int s = 0; s < 16; s++) dot += red[(pb * 16 + pj) * 17 + s];
        if (pj < 2) {
            float gsum = 0.f;
#pragma unroll
            for (int s = 0; s < 16; s++) {
                float2 v = ((float2*)zrj)[s * 16 + pb];
                gsum += (pj == 0) ? v.x : v.y;
            }
            float arg = xzr_v + gsum + ((pj == 0) ? zub : rub);
            float g = 1.f / (1.f + expf(-arg));   // precise exp: 512-step recurrence safety
            if (pj == 0) zg_s[pb] = g; else rg_s[pb] = g;
        }
        __syncthreads();
        float zg   = zg_s[pb], rg = rg_s[pb];
        float nt   = tanhf(xn_v + (dot + hubv) * rg);
        float hold = h_s[pb * HS_STRIDE + jg];
        float hn   = zg * hold + (1.f - zg) * nt;

        // streaming stores: bypass L1 allocate (never re-read through this SM's L1)
        __stcg(&out[((size_t)t * B_DIM + pbg) * H_DIM + jg], hn);
        __stcg(&g_hbuf[t & 1][pbg * H_DIM + jg], hn);
        if (hid_out != nullptr && t == T_DIM - 1) hid_out[pbg * H_DIM + jg] = hn;

        // prefetch NEXT step's time-parallel terms before the barrier:
        // g_xn/g_xz/g_xr are immutable during the scan, so this is safe and
        // overlaps DRAM latency with barrier wait.
        if (t != T_DIM - 1) {
            xn_v = __ldg(&g_xn[((size_t)(t + 1) * B_DIM + pbg) * H_DIM + jg]);
            if (pj == 0)      xzr_v = __ldg(&g_xz[(t + 1) * B_DIM + pbg]);
            else if (pj == 1) xzr_v = __ldg(&g_xr[(t + 1) * B_DIM + pbg]);

            // global barrier (sense-reversing via generation counter)
            __threadfence();
            __syncthreads();
            if (tid == 0) {
                unsigned my = atomicAdd(&g_count, 1u);
                if (my == NCTA - 1) {
                    atomicExch(&g_count, 0u);
                    __threadfence();
                    atomicAdd(&g_gen, 1u);
                } else {
                    while (ld_acquire_gpu(&g_gen) < gen_expect) { __nanosleep(64); }
                }
            }
            __syncthreads();
            gen_expect++;
        }
    }
}

// ---------------- launcher ----------------
extern "C" void kernel_launch(void* const* d_in, const int* in_sizes, int n_in,
                              void* d_out, int out_size) {
    const float* input  = (const float*)d_in[0];
    const float* hidden = (const float*)d_in[1];
    const float* zt_w_w = (const float*)d_in[2];
    const float* zt_w_b = (const float*)d_in[3];
    const float* zt_u_w = (const float*)d_in[4];
    const float* zt_u_b = (const float*)d_in[5];
    const float* rt_w_w = (const float*)d_in[6];
    const float* rt_w_b = (const float*)d_in[7];
    const float* rt_u_w = (const float*)d_in[8];
    const float* rt_u_b = (const float*)d_in[9];
    const float* h_w_w  = (const float*)d_in[10];
    const float* h_w_b  = (const float*)d_in[11];
    const float* h_u_w  = (const float*)d_in[12];
    const float* h_u_b  = (const float*)d_in[13];

    float* out = (float*)d_out;
    const long long seq_elems = (long long)T_DIM * B_DIM * H_DIM;
    float* hid_out = ((long long)out_size > seq_elems) ? out + seq_elems : nullptr;

    cudaFuncSetAttribute(k_scan, cudaFuncAttributeMaxDynamicSharedMemorySize, SCAN_SMEM_BYTES);

    // 1) xz/xr GEMVs (+ reset of barrier state)
    k_xzr<<<(T_DIM * B_DIM * 32 + 255) / 256, 256>>>(input, zt_w_w, zt_w_b, rt_w_w, rt_w_b);
    // 2) big time-parallel GEMM: xn
    dim3 gx(H_DIM / BN, (T_DIM * B_DIM) / BM);
    k_xn<<<gx, 256>>>(input, h_w_w, h_w_b);
    // 3) persistent sequential scan
    k_scan<<<NCTA, 256, SCAN_SMEM_BYTES>>>(hidden, h_u_w, h_u_b,
                                           zt_u_w, zt_u_b, rt_u_w, rt_u_b,
                                           out, hid_out);
}

// round 13
// speedup vs baseline: 1.0022x; 1.0022x over previous
#include <cuda_runtime.h>
#include <cstdint>
#include <cstddef>

#define T_DIM 512
#define B_DIM 64
#define I_DIM 512
#define H_DIM 512
#define NCTA 128
#define HS_STRIDE 516  /* 512 + 4 pad */

typedef unsigned long long ull;

// ---------------- device scratch (allocation-free: __device__ globals) ----------------
__device__ float g_xn[(size_t)T_DIM * B_DIM * H_DIM];   // 64 MB precomputed input projection
__device__ float g_xz[T_DIM * B_DIM];
__device__ float g_xr[T_DIM * B_DIM];
__device__ float g_hbuf[2][B_DIM * H_DIM];              // double-buffered hidden state
// flag-line barrier state: per batch-group (4 groups x 32 CTAs).
// g_flag[bg] = one 128B line of 32 per-CTA flag words -> arrival is ONE release
// store to a DISTINCT word (no same-address atomic serialization).
__device__ __align__(128) unsigned g_flag[4][32];
__device__ __align__(128) unsigned g_genl[4][32];       // gen word per bg (padded line)

// ---------------- packed f32x2 helpers (Blackwell FFMA2) ----------------
__device__ __forceinline__ ull ffma2(ull a, ull b, ull c) {
    ull d; asm("fma.rn.f32x2 %0, %1, %2, %3;" : "=l"(d) : "l"(a), "l"(b), "l"(c)); return d;
}
__device__ __forceinline__ ull fpack2(float x, float y) {
    ull d; asm("mov.b64 %0, {%1, %2};" : "=l"(d) : "f"(x), "f"(y)); return d;
}
__device__ __forceinline__ float2 funpack2(ull a) {
    float2 r; asm("mov.b64 {%0, %1}, %2;" : "=f"(r.x), "=f"(r.y) : "l"(a)); return r;
}
__device__ __forceinline__ unsigned ld_acquire_gpu(const unsigned* p) {
    unsigned v; asm volatile("ld.acquire.gpu.u32 %0, [%1];" : "=r"(v) : "l"(p) : "memory");
    return v;
}
__device__ __forceinline__ void st_release_gpu(unsigned* p, unsigned v) {
    asm volatile("st.release.gpu.u32 [%0], %1;" :: "l"(p), "r"(v) : "memory");
}

// ---------------- kernel 1: xz/xr projections (warp per row) + barrier state reset ----
__global__ void k_xzr(const float* __restrict__ inp, const float* __restrict__ zw,
                      const float* __restrict__ zb, const float* __restrict__ rw,
                      const float* __restrict__ rb) {
    if (blockIdx.x == 0 && threadIdx.x < 128) {
        g_flag[threadIdx.x >> 5][threadIdx.x & 31] = 0;
        if (threadIdx.x < 4) g_genl[threadIdx.x][0] = 0;
    }
    int gw   = (blockIdx.x * blockDim.x + threadIdx.x) >> 5;
    int lane = threadIdx.x & 31;
    if (gw >= T_DIM * B_DIM) return;
    const float4* row = (const float4*)(inp + (size_t)gw * I_DIM);
    const float4* z4  = (const float4*)zw;
    const float4* r4  = (const float4*)rw;
    float za = 0.f, ra = 0.f;
#pragma unroll
    for (int i = 0; i < 4; i++) {
        float4 v  = row[lane + 32 * i];
        float4 zz = __ldg(&z4[lane + 32 * i]);
        float4 rr = __ldg(&r4[lane + 32 * i]);
        za += v.x * zz.x + v.y * zz.y + v.z * zz.z + v.w * zz.w;
        ra += v.x * rr.x + v.y * rr.y + v.z * rr.z + v.w * rr.w;
    }
#pragma unroll
    for (int off = 16; off > 0; off >>= 1) {
        za += __shfl_down_sync(0xffffffffu, za, off);
        ra += __shfl_down_sync(0xffffffffu, ra, off);
    }
    if (lane == 0) {
        g_xz[gw] = za + __ldg(zb);
        g_xr[gw] = ra + __ldg(rb);
    }
}

// ---------------- kernel 2: xn = input @ h_w_w^T + h_w_b  (FFMA2 SGEMM) ----------------
#define BM 128
#define BN 128
#define BK 16
__global__ __launch_bounds__(256) void k_xn(const float* __restrict__ A,
                                            const float* __restrict__ W,
                                            const float* __restrict__ bias) {
    __shared__ float As[BK][BM + 4];
    __shared__ float Bs[BK][BN + 4];
    const int tid  = threadIdx.x;
    const int mblk = blockIdx.y * BM;
    const int nblk = blockIdx.x * BN;
    const int tn   = (tid & 15) * 8;
    const int tm   = (tid >> 4) * 8;

    ull acc[8][4];
#pragma unroll
    for (int i = 0; i < 8; i++)
#pragma unroll
        for (int p = 0; p < 4; p++) acc[i][p] = 0ull;

    for (int k0 = 0; k0 < I_DIM; k0 += BK) {
#pragma unroll
        for (int i = 0; i < 2; i++) {
            int id = tid + 256 * i;
            int m = id >> 2, kq = id & 3;
            float4 av = *(const float4*)(A + (size_t)(mblk + m) * I_DIM + k0 + kq * 4);
            As[kq * 4 + 0][m] = av.x; As[kq * 4 + 1][m] = av.y;
            As[kq * 4 + 2][m] = av.z; As[kq * 4 + 3][m] = av.w;
            float4 bv = *(const float4*)(W + (size_t)(nblk + m) * I_DIM + k0 + kq * 4);
            Bs[kq * 4 + 0][m] = bv.x; Bs[kq * 4 + 1][m] = bv.y;
            Bs[kq * 4 + 2][m] = bv.z; Bs[kq * 4 + 3][m] = bv.w;
        }
        __syncthreads();
#pragma unroll
        for (int k = 0; k < BK; k++) {
            float4 a0 = *(const float4*)&As[k][tm];
            float4 a1 = *(const float4*)&As[k][tm + 4];
            ulonglong2 b0 = *(const ulonglong2*)&Bs[k][tn];
            ulonglong2 b1 = *(const ulonglong2*)&Bs[k][tn + 4];
            ull bb[4] = { b0.x, b0.y, b1.x, b1.y };
            float a[8] = { a0.x, a0.y, a0.z, a0.w, a1.x, a1.y, a1.z, a1.w };
#pragma unroll
            for (int i = 0; i < 8; i++) {
                ull ad = fpack2(a[i], a[i]);
#pragma unroll
                for (int p = 0; p < 4; p++) acc[i][p] = ffma2(ad, bb[p], acc[i][p]);
            }
        }
        __syncthreads();
    }
    float4 bvlo = *(const float4*)(bias + nblk + tn);
    float4 bvhi = *(const float4*)(bias + nblk + tn + 4);
#pragma unroll
    for (int i = 0; i < 8; i++) {
        float2 c0 = funpack2(acc[i][0]);
        float2 c1 = funpack2(acc[i][1]);
        float2 c2 = funpack2(acc[i][2]);
        float2 c3 = funpack2(acc[i][3]);
        float4 o0 = make_float4(c0.x + bvlo.x, c0.y + bvlo.y, c1.x + bvlo.z, c1.y + bvlo.w);
        float4 o1 = make_float4(c2.x + bvhi.x, c2.y + bvhi.y, c3.x + bvhi.z, c3.y + bvhi.w);
        float* outp = g_xn + (size_t)(mblk + tm + i) * H_DIM + nblk + tn;
        *(float4*)outp       = o0;
        *(float4*)(outp + 4) = o1;
    }
}

// ---------------- kernel 3: persistent GRU scan ----------------
// 128 CTAs = 32 col-groups x 4 batch-groups; CTA owns a 16(b) x 16(h) tile.
// h_u_w tile in REGISTERS. The 4 batch groups are INDEPENDENT recurrences ->
// 4 independent 32-CTA flag-line barriers (no atomics, no membar, no nanosleep).
#define SCAN_SMEM_FLOATS (16 * HS_STRIDE + 16 * 16 * 17 + 512 + 576 + 576 + 16 + 16)
#define SCAN_SMEM_BYTES  (SCAN_SMEM_FLOATS * 4)

__global__ __launch_bounds__(256) void k_scan(
    const float* __restrict__ hidden, const float* __restrict__ huw,
    const float* __restrict__ hub, const float* __restrict__ zuw,
    const float* __restrict__ zubp, const float* __restrict__ ruw,
    const float* __restrict__ rubp, float* __restrict__ out,
    float* __restrict__ hid_out) {
    extern __shared__ float sm[];
    float* h_s  = sm;                         // [16][HS_STRIDE]
    float* red  = sm + 16 * HS_STRIDE;        // [16b][16j][17] partials
    float* zrj  = red + 16 * 16 * 17;         // float2 [16 ks][16 b] gate partials
    float* zu_s = zrj + 512;                  // padded: idx k + 4*(k>>5)
    float* ru_s = zu_s + 576;
    float* zg_s = ru_s + 576;                 // [16]
    float* rg_s = zg_s + 16;                  // [16]

    const int tid = threadIdx.x;
    const int cg  = blockIdx.x & 31;   // col group (0..31)
    const int bg  = blockIdx.x >> 5;   // batch group (0..3)
    const int j   = tid & 15;
    const int ks  = tid >> 4;          // k-slice (32 k's each)
    const int jg  = cg * 16 + j;

    // h_u_w slice in registers: 32 floats = 16 packed pairs
    ull u2[16];
    {
        const ulonglong2* up = (const ulonglong2*)(huw + (size_t)jg * H_DIM + ks * 32);
#pragma unroll
        for (int q = 0; q < 8; q++) { ulonglong2 v = up[q]; u2[2 * q] = v.x; u2[2 * q + 1] = v.y; }
    }
    const float zub  = *zubp;
    const float rub  = *rubp;
    const float hubv = hub[jg];
    for (int i = tid; i < 512; i += 256) {
        int d = i + 4 * (i >> 5);
        zu_s[d] = zuw[i];
        ru_s[d] = ruw[i];
    }
    const int gb  = tid & 15, gks = tid >> 4;   // gate-phase mapping
    const int pb  = tid >> 4, pj = tid & 15;    // phase-2 mapping (pj == j)
    const int pbg = bg * 16 + pb;
    __syncthreads();

    // prefetch step-0 time-parallel terms
    float xn_v  = __ldg(&g_xn[((size_t)0 * B_DIM + pbg) * H_DIM + jg]);
    float xzr_v = 0.f;
    if (pj == 0)      xzr_v = __ldg(&g_xz[pbg]);
    else if (pj == 1) xzr_v = __ldg(&g_xr[pbg]);

    for (int t = 0; t < T_DIM; t++) {
        const float* hsrc = (t == 0) ? hidden : g_hbuf[(t + 1) & 1];

        // stage h tile 16x512 into smem (L2 loads; peer CTAs of same bg wrote it)
#pragma unroll
        for (int i = 0; i < 8; i++) {
            int id = i * 256 + tid;
            int r = id >> 7, c4 = id & 127;
            float4 v = __ldcg((const float4*)(hsrc + (size_t)(bg * 16 + r) * H_DIM) + c4);
            *(float4*)&h_s[r * HS_STRIDE + c4 * 4] = v;
        }
        __syncthreads();

        // gate partial dots (z and r), per (batch, k-slice)
        {
            ull za = 0ull, ra = 0ull;
#pragma unroll
            for (int c = 0; c < 8; c++) {
                ulonglong2 hv = *(const ulonglong2*)&h_s[gb * HS_STRIDE + gks * 32 + c * 4];
                ulonglong2 zv = *(const ulonglong2*)&zu_s[gks * 36 + c * 4];
                ulonglong2 rv = *(const ulonglong2*)&ru_s[gks * 36 + c * 4];
                za = ffma2(hv.x, zv.x, za); za = ffma2(hv.y, zv.y, za);
                ra = ffma2(hv.x, rv.x, ra); ra = ffma2(hv.y, rv.y, ra);
            }
            float2 zf = funpack2(za), rf = funpack2(ra);
            ((float2*)zrj)[gks * 16 + gb] = make_float2(zf.x + zf.y, rf.x + rf.y);
        }

        // main GEMM partials: h[16 b, 32 k] . u2 (registers); h LDS is 16-lane broadcast
        {
            ull acc[16];
#pragma unroll
            for (int b = 0; b < 16; b++) acc[b] = 0ull;
#pragma unroll
            for (int c = 0; c < 8; c++) {
                ull ua = u2[2 * c], ub = u2[2 * c + 1];
#pragma unroll
                for (int b = 0; b < 16; b++) {
                    ulonglong2 hv = *(const ulonglong2*)&h_s[b * HS_STRIDE + ks * 32 + c * 4];
                    acc[b] = ffma2(hv.x, ua, acc[b]);
                    acc[b] = ffma2(hv.y, ub, acc[b]);
                }
            }
#pragma unroll
            for (int b = 0; b < 16; b++) {
                float2 f = funpack2(acc[b]);
                red[(b * 16 + j) * 17 + ks] = f.x + f.y;
            }
        }
        __syncthreads();

        // phase 2: reduce k-slices; finalize gates; elementwise GRU update
        float dot = 0.f;
#pragma unroll
        for (int s = 0; s < 16; s++) dot += red[(pb * 16 + pj) * 17 + s];
        if (pj < 2) {
            float gsum = 0.f;
#pragma unroll
            for (int s = 0; s < 16; s++) {
                float2 v = ((float2*)zrj)[s * 16 + pb];
                gsum += (pj == 0) ? v.x : v.y;
            }
            float arg = xzr_v + gsum + ((pj == 0) ? zub : rub);
            float g = 1.f / (1.f + expf(-arg));   // precise exp: 512-step recurrence safety
            if (pj == 0) zg_s[pb] = g; else rg_s[pb] = g;
        }
        __syncthreads();
        float zg   = zg_s[pb], rg = rg_s[pb];
        float nt   = tanhf(xn_v + (dot + hubv) * rg);
        float hold = h_s[pb * HS_STRIDE + jg];
        float hn   = zg * hold + (1.f - zg) * nt;

        // hidden for next step must be globally visible before arrival
        __stcg(&g_hbuf[t & 1][pbg * H_DIM + jg], hn);
        if (hid_out != nullptr && t == T_DIM - 1) hid_out[pbg * H_DIM + jg] = hn;

        if (t != T_DIM - 1) {
            // prefetch NEXT step's time-parallel terms (immutable data; overlaps wait)
            float nxn = __ldg(&g_xn[((size_t)(t + 1) * B_DIM + pbg) * H_DIM + jg]);
            float nxzr = 0.f;
            if (pj == 0)      nxzr = __ldg(&g_xz[(t + 1) * B_DIM + pbg]);
            else if (pj == 1) nxzr = __ldg(&g_xr[(t + 1) * B_DIM + pbg]);

            __syncthreads();                       // all hbuf stores of this CTA issued
            if (tid == 0) st_release_gpu(&g_flag[bg][cg], (unsigned)(t + 1));

            // out store overlaps the barrier wait (nobody reads it)
            __stcg(&out[((size_t)t * B_DIM + pbg) * H_DIM + jg], hn);

            if (cg == 0 && tid < 32) {
                // poller warp: one coalesced 128B load per poll of all 32 flags
                for (;;) {
                    unsigned v = ld_acquire_gpu(&g_flag[bg][tid]);
                    if (__all_sync(0xffffffffu, v >= (unsigned)(t + 1))) break;
                }
                if (tid == 0) st_release_gpu(&g_genl[bg][0], (unsigned)(t + 1));
            } else if (tid == 0) {
                while (ld_acquire_gpu(&g_genl[bg][0]) < (unsigned)(t + 1)) {}
            }
            __syncthreads();                       // propagate acquire to whole CTA
            xn_v = nxn; xzr_v = nxzr;
        } else {
            __stcg(&out[((size_t)t * B_DIM + pbg) * H_DIM + jg], hn);
        }
    }
}

// ---------------- launcher ----------------
extern "C" void kernel_launch(void* const* d_in, const int* in_sizes, int n_in,
                              void* d_out, int out_size) {
    const float* input  = (const float*)d_in[0];
    const float* hidden = (const float*)d_in[1];
    const float* zt_w_w = (const float*)d_in[2];
    const float* zt_w_b = (const float*)d_in[3];
    const float* zt_u_w = (const float*)d_in[4];
    const float* zt_u_b = (const float*)d_in[5];
    const float* rt_w_w = (const float*)d_in[6];
    const float* rt_w_b = (const float*)d_in[7];
    const float* rt_u_w = (const float*)d_in[8];
    const float* rt_u_b = (const float*)d_in[9];
    const float* h_w_w  = (const float*)d_in[10];
    const float* h_w_b  = (const float*)d_in[11];
    const float* h_u_w  = (const float*)d_in[12];
    const float* h_u_b  = (const float*)d_in[13];

    float* out = (float*)d_out;
    const long long seq_elems = (long long)T_DIM * B_DIM * H_DIM;
    float* hid_out = ((long long)out_size > seq_elems) ? out + seq_elems : nullptr;

    cudaFuncSetAttribute(k_scan, cudaFuncAttributeMaxDynamicSharedMemorySize, SCAN_SMEM_BYTES);

    // 1) xz/xr GEMVs (+ reset of barrier state)
    k_xzr<<<(T_DIM * B_DIM * 32 + 255) / 256, 256>>>(input, zt_w_w, zt_w_b, rt_w_w, rt_w_b);
    // 2) big time-parallel GEMM: xn
    dim3 gx(H_DIM / BN, (T_DIM * B_DIM) / BM);
    k_xn<<<gx, 256>>>(input, h_w_w, h_w_b);
    // 3) persistent sequential scan
    k_scan<<<NCTA, 256, SCAN_SMEM_BYTES>>>(hidden, h_u_w, h_u_b,
                                           zt_u_w, zt_u_b, rt_u_w, rt_u_b,
                                           out, hid_out);
}